// round 14
// baseline (speedup 1.0000x reference)
#include <cuda_runtime.h>
#include <cstdint>

// Problem constants (fixed by the reference: SHAPE = (8192, 4096), P = 0.3)
#define N_ELEMS   (8192 * 4096)        // 33,554,432 floats
#define N_FLOAT4  (N_ELEMS / 4)        // 8,388,608 float4s

// Byte-mask scratch: 1 byte per element (32 MB, fits L2 alongside streaming
// .cs traffic). Zero at module load; apply re-zeroes it every pass for the
// next graph replay (self-cleaning). Plain stores of 1 are idempotent ->
// no atomics needed, skipping the LTS read-modify-write ALU (the measured
// bottleneck: R13 pure scatter ran at L2=77.8% with ~2 cyc/RED per slice).
__device__ uint8_t g_maskb[N_ELEMS];

// ---------------------------------------------------------------------------
// Kernel 1: scatter-mark bytes from the int32 index list.
// Flat launch: one int4 idx load + 4 fire-and-forget STG.8 per thread.
// ---------------------------------------------------------------------------
__global__ void set_bytes_kernel(const int4* __restrict__ idx4, int n_quads,
                                 int k) {
    int i = blockIdx.x * blockDim.x + threadIdx.x;
    if (i < n_quads) {
        int4 v = __ldcs(&idx4[i]);
        g_maskb[(unsigned int)v.x] = 1;
        g_maskb[(unsigned int)v.y] = 1;
        g_maskb[(unsigned int)v.z] = 1;
        g_maskb[(unsigned int)v.w] = 1;
    }
    // tail (k % 4 != 0)
    if (i == 0) {
        const int* idx = (const int*)idx4;
        for (int j = n_quads * 4; j < k; j++) {
            g_maskb[(unsigned int)idx[j]] = 1;
        }
    }
}

// ---------------------------------------------------------------------------
// Kernel 2: fused copy + masked zero + mask self-clean.
// 256 threads, ILP=4 block-strided, block covers 1024 consecutive float4s
// (best-measured apply config). Each float4 i pairs with mask word
// mask32[i] (4 bytes covering elements 4i..4i+3) — PRIVATE to the thread:
// coalesced uint32 loads, and the self-clean store needs no warp-order
// argument at all. X read .cs, out written .cs (keeps mask L2-resident).
// ---------------------------------------------------------------------------
__global__ void __launch_bounds__(256)
apply_mask_kernel(const float4* __restrict__ X, float4* __restrict__ out) {
    uint32_t* mask32 = (uint32_t*)g_maskb;
    int tid = threadIdx.x;
    int base = blockIdx.x * 1024 + tid;
    int i0 = base, i1 = base + 256, i2 = base + 512, i3 = base + 768;

    uint32_t m0 = mask32[i0];
    uint32_t m1 = mask32[i1];
    uint32_t m2 = mask32[i2];
    uint32_t m3 = mask32[i3];
    float4 v0 = __ldcs(&X[i0]);
    float4 v1 = __ldcs(&X[i1]);
    float4 v2 = __ldcs(&X[i2]);
    float4 v3 = __ldcs(&X[i3]);

    if (m0 & 0x000000FFu) v0.x = 0.0f;
    if (m0 & 0x0000FF00u) v0.y = 0.0f;
    if (m0 & 0x00FF0000u) v0.z = 0.0f;
    if (m0 & 0xFF000000u) v0.w = 0.0f;
    __stcs(&out[i0], v0);

    if (m1 & 0x000000FFu) v1.x = 0.0f;
    if (m1 & 0x0000FF00u) v1.y = 0.0f;
    if (m1 & 0x00FF0000u) v1.z = 0.0f;
    if (m1 & 0xFF000000u) v1.w = 0.0f;
    __stcs(&out[i1], v1);

    if (m2 & 0x000000FFu) v2.x = 0.0f;
    if (m2 & 0x0000FF00u) v2.y = 0.0f;
    if (m2 & 0x00FF0000u) v2.z = 0.0f;
    if (m2 & 0xFF000000u) v2.w = 0.0f;
    __stcs(&out[i2], v2);

    if (m3 & 0x000000FFu) v3.x = 0.0f;
    if (m3 & 0x0000FF00u) v3.y = 0.0f;
    if (m3 & 0x00FF0000u) v3.z = 0.0f;
    if (m3 & 0xFF000000u) v3.w = 0.0f;
    __stcs(&out[i3], v3);

    // self-clean own mask words for the next graph replay (private words ->
    // no races possible; coalesced full-line stores)
    mask32[i0] = 0u;
    mask32[i1] = 0u;
    mask32[i2] = 0u;
    mask32[i3] = 0u;
}

extern "C" void kernel_launch(void* const* d_in, const int* in_sizes, int n_in,
                              void* d_out, int out_size) {
    const float* X = (const float*)d_in[0];
    const int* drop_idx = (const int*)d_in[1];   // JAX x64-disabled => int32
    int k = in_sizes[1];                          // number of indices
    float* out = (float*)d_out;

    // 1) scatter mark bytes (mask zero: module init or previous apply)
    {
        int n_quads = k / 4;
        int threads = 256;
        int blocks = (n_quads + threads - 1) / threads;   // flat, wide
        set_bytes_kernel<<<blocks, threads>>>((const int4*)drop_idx, n_quads,
                                              k);
    }

    // 2) fused copy + zero + mask clean (1024 float4s per 256-thread block)
    {
        int blocks = N_FLOAT4 / 1024;   // 8192
        apply_mask_kernel<<<blocks, 256>>>((const float4*)X, (float4*)out);
    }
}

// round 15
// speedup vs baseline: 1.4079x; 1.4079x over previous
#include <cuda_runtime.h>
#include <cstdint>

// Problem constants (fixed by the reference: SHAPE = (8192, 4096), P = 0.3)
#define N_ELEMS   (8192 * 4096)        // 33,554,432 floats
#define N_WORDS   (N_ELEMS / 32)       // 1,048,576 uint32 mask words = 4 MB
#define N_FLOAT4  (N_ELEMS / 4)        // 8,388,608 float4s

// Scratch: 1 bit per element, 4 MB -> stays L2-resident so every RED.OR is
// an L2-hit RMW (~2 cyc/LTS slot; the measured scatter floor). Zero at
// module load; apply re-zeroes it every pass (self-cleaning).
__device__ uint32_t g_mask[N_WORDS];

// ---------------------------------------------------------------------------
// Kernel 1: scatter-set bits. Flat, one int4 idx load + 4 fire-and-forget
// RED.ORs per thread (best-measured shape). Each block triggers the
// dependent launch right after issuing its REDs — the PDL trigger carries
// the visibility guarantee, so the apply kernel may start its X loads while
// this grid's REDs drain through LTS.
// ---------------------------------------------------------------------------
__global__ void set_bits_kernel(const int4* __restrict__ idx4, int n_quads,
                                int k) {
    int i = blockIdx.x * blockDim.x + threadIdx.x;
    if (i < n_quads) {
        int4 v = __ldcs(&idx4[i]);
        unsigned int a = (unsigned int)v.x;
        unsigned int b = (unsigned int)v.y;
        unsigned int c = (unsigned int)v.z;
        unsigned int d = (unsigned int)v.w;
        atomicOr(&g_mask[a >> 5], 1u << (a & 31));
        atomicOr(&g_mask[b >> 5], 1u << (b & 31));
        atomicOr(&g_mask[c >> 5], 1u << (c & 31));
        atomicOr(&g_mask[d >> 5], 1u << (d & 31));
    }
    // tail (k % 4 != 0)
    if (i == 0) {
        const int* idx = (const int*)idx4;
        for (int j = n_quads * 4; j < k; j++) {
            unsigned int a = (unsigned int)idx[j];
            atomicOr(&g_mask[a >> 5], 1u << (a & 31));
        }
    }
    cudaTriggerProgrammaticLaunchCompletion();
}

// ---------------------------------------------------------------------------
// Kernel 2: fused copy + masked zero + mask self-clean (best-measured R4
// config: 256 threads, ILP=4 block-strided, 1024 consecutive float4s per
// block, coalesced). PDL ordering: issue ALL X loads first (DRAM traffic
// that legally overlaps the scatter), then cudaGridDependencySynchronize()
// (no-op if launched without PDL), then read the mask.
// 8 adjacent same-warp threads share one mask word; the (tid&7)==0 lane
// cleans AFTER the group's mask loads (same warp -> program order).
// ---------------------------------------------------------------------------
__global__ void __launch_bounds__(256)
apply_mask_kernel(const float4* __restrict__ X, float4* __restrict__ out) {
    int tid = threadIdx.x;
    int base = blockIdx.x * 1024 + tid;
    int i0 = base, i1 = base + 256, i2 = base + 512, i3 = base + 768;

    // X loads first: independent of the scatter, may fly under its tail.
    float4 v0 = __ldcs(&X[i0]);
    float4 v1 = __ldcs(&X[i1]);
    float4 v2 = __ldcs(&X[i2]);
    float4 v3 = __ldcs(&X[i3]);

    // Wait for the scatter grid's memory to be visible.
    cudaGridDependencySynchronize();

    uint32_t w0 = g_mask[i0 >> 3];
    uint32_t w1 = g_mask[i1 >> 3];
    uint32_t w2 = g_mask[i2 >> 3];
    uint32_t w3 = g_mask[i3 >> 3];

    uint32_t n0 = w0 >> ((i0 & 7) * 4);
    if (n0 & 1u) v0.x = 0.0f;
    if (n0 & 2u) v0.y = 0.0f;
    if (n0 & 4u) v0.z = 0.0f;
    if (n0 & 8u) v0.w = 0.0f;
    __stcs(&out[i0], v0);

    uint32_t n1 = w1 >> ((i1 & 7) * 4);
    if (n1 & 1u) v1.x = 0.0f;
    if (n1 & 2u) v1.y = 0.0f;
    if (n1 & 4u) v1.z = 0.0f;
    if (n1 & 8u) v1.w = 0.0f;
    __stcs(&out[i1], v1);

    uint32_t n2 = w2 >> ((i2 & 7) * 4);
    if (n2 & 1u) v2.x = 0.0f;
    if (n2 & 2u) v2.y = 0.0f;
    if (n2 & 4u) v2.z = 0.0f;
    if (n2 & 8u) v2.w = 0.0f;
    __stcs(&out[i2], v2);

    uint32_t n3 = w3 >> ((i3 & 7) * 4);
    if (n3 & 1u) v3.x = 0.0f;
    if (n3 & 2u) v3.y = 0.0f;
    if (n3 & 4u) v3.z = 0.0f;
    if (n3 & 8u) v3.w = 0.0f;
    __stcs(&out[i3], v3);

    // self-clean for next graph replay (one lane per 8-thread group cleans
    // that group's four mask words; same warp as all readers of those words)
    if ((tid & 7) == 0) {
        g_mask[i0 >> 3] = 0u;
        g_mask[i1 >> 3] = 0u;
        g_mask[i2 >> 3] = 0u;
        g_mask[i3 >> 3] = 0u;
    }
}

extern "C" void kernel_launch(void* const* d_in, const int* in_sizes, int n_in,
                              void* d_out, int out_size) {
    const float* X = (const float*)d_in[0];
    const int* drop_idx = (const int*)d_in[1];   // JAX x64-disabled => int32
    int k = in_sizes[1];                          // number of indices
    float* out = (float*)d_out;

    // 1) scatter bits (mask is zero: module init or previous apply)
    {
        int n_quads = k / 4;
        int threads = 256;
        int blocks = (n_quads + threads - 1) / threads;   // flat, wide
        set_bits_kernel<<<blocks, threads>>>((const int4*)drop_idx, n_quads,
                                             k);
    }

    // 2) fused copy + zero + mask clean, launched with programmatic stream
    //    serialization so it can ramp while the scatter's REDs drain.
    {
        cudaLaunchConfig_t cfg = {};
        cfg.gridDim = dim3(N_FLOAT4 / 1024, 1, 1);   // 8192
        cfg.blockDim = dim3(256, 1, 1);
        cudaLaunchAttribute attr[1];
        attr[0].id = cudaLaunchAttributeProgrammaticStreamSerialization;
        attr[0].val.programmaticStreamSerializationAllowed = 1;
        cfg.attrs = attr;
        cfg.numAttrs = 1;
        cudaError_t e = cudaLaunchKernelEx(&cfg, apply_mask_kernel,
                                           (const float4*)X, (float4*)out);
        if (e != cudaSuccess) {
            // PDL unavailable (e.g. capture restriction): plain launch.
            apply_mask_kernel<<<N_FLOAT4 / 1024, 256>>>((const float4*)X,
                                                        (float4*)out);
        }
    }
}